// round 11
// baseline (speedup 1.0000x reference)
#include <cuda_runtime.h>
#include <cuda_bf16.h>
#include <mma.h>
#include <cstdint>
#include <math.h>

using namespace nvcuda;

#define NB 2
#define SLEN 2048
#define NHEADS 16
#define HDIM 64
#define EMB 1024
#define NH (NB * NHEADS)
#define NROWS (NB * SLEN * NHEADS)

// ---------------------------------------------------------------------------
// Global scratch (allocation-free rule: __device__ globals)
// ---------------------------------------------------------------------------
__device__ __align__(16) __nv_bfloat16 g_qh[(size_t)NH * SLEN * HDIM];
__device__ __align__(16) __nv_bfloat16 g_ql[(size_t)NH * SLEN * HDIM];
__device__ __align__(16) __nv_bfloat16 g_kh[(size_t)NH * SLEN * HDIM];
__device__ __align__(16) __nv_bfloat16 g_kl[(size_t)NH * SLEN * HDIM];
__device__ __align__(16) __nv_bfloat16 g_vh[(size_t)NH * SLEN * HDIM];
__device__ __align__(16) __nv_bfloat16 g_vl[(size_t)NH * SLEN * HDIM];
__device__ __align__(16) __nv_bfloat16 g_oh[(size_t)NB * SLEN * EMB];   // attn out hi
__device__ __align__(16) __nv_bfloat16 g_ol[(size_t)NB * SLEN * EMB];   // attn out lo
__device__ __align__(16) __nv_bfloat16 g_woth[(size_t)EMB * EMB];       // Wo^T hi (e,k)
__device__ __align__(16) __nv_bfloat16 g_wotl[(size_t)EMB * EMB];       // Wo^T lo (e,k)

__device__ __forceinline__ uint32_t pack_bf2(float a, float b) {
    __nv_bfloat16 x = __float2bfloat16(a), y = __float2bfloat16(b);
    return ((uint32_t)__bfloat16_as_ushort(y) << 16) | (uint32_t)__bfloat16_as_ushort(x);
}
__device__ __forceinline__ float bf_round(float a) {
    return __bfloat162float(__float2bfloat16(a));
}

// ---------------------------------------------------------------------------
// Kernel 1: per-head projection -> bf16 hi/lo splits in (N,H,S,D)
// ---------------------------------------------------------------------------
__global__ __launch_bounds__(256) void proj_kernel(
    const float* __restrict__ in, const float* __restrict__ W,
    const float* __restrict__ bias, int which, float scale)
{
    __shared__ float in_s[64 * 65];
    __shared__ float w_s[64 * 64];

    __nv_bfloat16* outh = (which == 0) ? g_vh : (which == 1) ? g_kh : g_qh;
    __nv_bfloat16* outl = (which == 0) ? g_vl : (which == 1) ? g_kl : g_ql;

    int t = threadIdx.x;
    int rowBase = blockIdx.x * 64;

    for (int i = t; i < 4096; i += 256) w_s[i] = W[i];
    for (int i = t; i < 4096; i += 256) {
        int r = i >> 6, k = i & 63;
        in_s[r * 65 + k] = in[(size_t)rowBase * 64 + i];
    }
    __syncthreads();

    int tr = t >> 4, tc = t & 15;
    int r0 = tr * 4, c0 = tc * 4;

    float acc[4][4];
    #pragma unroll
    for (int u = 0; u < 4; u++)
        #pragma unroll
        for (int v = 0; v < 4; v++) acc[u][v] = bias[c0 + v];

    #pragma unroll 8
    for (int k = 0; k < 64; k++) {
        float4 b = *(const float4*)&w_s[k * 64 + c0];
        float a[4];
        #pragma unroll
        for (int u = 0; u < 4; u++) a[u] = in_s[(r0 + u) * 65 + k];
        #pragma unroll
        for (int u = 0; u < 4; u++) {
            acc[u][0] += a[u] * b.x; acc[u][1] += a[u] * b.y;
            acc[u][2] += a[u] * b.z; acc[u][3] += a[u] * b.w;
        }
    }

    #pragma unroll
    for (int u = 0; u < 4; u++) {
        int row = rowBase + r0 + u;
        int n = row >> 15;
        int rem = row & 32767;
        int s = rem >> 4;
        int h = rem & 15;
        size_t base = (((size_t)(n * NHEADS + h)) * SLEN + s) * HDIM + c0;
        float v0 = acc[u][0] * scale, v1 = acc[u][1] * scale;
        float v2 = acc[u][2] * scale, v3 = acc[u][3] * scale;
        *(uint32_t*)&outh[base + 0] = pack_bf2(v0, v1);
        *(uint32_t*)&outh[base + 2] = pack_bf2(v2, v3);
        *(uint32_t*)&outl[base + 0] = pack_bf2(v0 - bf_round(v0), v1 - bf_round(v1));
        *(uint32_t*)&outl[base + 2] = pack_bf2(v2 - bf_round(v2), v3 - bf_round(v3));
    }
}

// ---------------------------------------------------------------------------
// Kernel 2: transpose + split Wo -> WoT hi/lo (e,k)
// ---------------------------------------------------------------------------
__global__ __launch_bounds__(256) void wo_convert(const float* __restrict__ Wo)
{
    __shared__ float ts[64 * 65];
    int t = threadIdx.x;
    int kb = blockIdx.x * 64, eb = blockIdx.y * 64;
    for (int i = t; i < 4096; i += 256) {
        int r = i >> 6, c = i & 63;
        ts[c * 65 + r] = Wo[(size_t)(kb + r) * EMB + eb + c];
    }
    __syncthreads();
    for (int i = t; i < 4096; i += 256) {
        int e = i >> 6, k = i & 63;
        float v = ts[e * 65 + k];
        size_t o = (size_t)(eb + e) * EMB + kb + k;
        g_woth[o] = __float2bfloat16(v);
        g_wotl[o] = __float2bfloat16(v - bf_round(v));
    }
}

// ---------------------------------------------------------------------------
// Kernel 3: WMMA flash attention. CTA = (qt, nh): 128 q-rows x full S.
// sf (f32 scores) ALIASED over ph/pl (P hi/lo) -> 109KB smem -> 2 CTAs/SM.
// Softmax uses all 256 threads (thread = (row, half)).
// ---------------------------------------------------------------------------
#define LDH 72                 // bf16 smem ldm
#define LDS 68                 // f32 smem ldm

#define A_QH 0
#define A_QL (A_QH + 128 * LDH * 2)          // 18432
#define A_KH (A_QL + 128 * LDH * 2)          // 36864
#define A_KL (A_KH + 64 * LDH * 2)           // 46080
#define A_VH (A_KL + 64 * LDH * 2)           // 55296
#define A_VL (A_VH + 64 * LDH * 2)           // 64512
#define A_PH (A_VL + 64 * LDH * 2)           // 73728
#define A_PL (A_PH + 128 * LDH * 2)          // 92160
#define A_SF A_PH                            // aliased: 34816 <= 36864
#define A_LS (A_PL + 128 * LDH * 2)          // 110592 (lsum partials, 256 f32)
#define ATTN_SMEM (A_LS + 256 * 4)           // 111616 (109KB) -> 2 CTAs/SM

typedef wmma::fragment<wmma::matrix_a, 16, 16, 16, __nv_bfloat16, wmma::row_major> FragA;
typedef wmma::fragment<wmma::matrix_b, 16, 16, 16, __nv_bfloat16, wmma::col_major> FragBC;
typedef wmma::fragment<wmma::matrix_b, 16, 16, 16, __nv_bfloat16, wmma::row_major> FragBR;
typedef wmma::fragment<wmma::accumulator, 16, 16, 16, float> FragC;

__global__ __launch_bounds__(256, 2) void attn_wmma(const float* __restrict__ mask)
{
    extern __shared__ char smem[];
    __nv_bfloat16* qh = (__nv_bfloat16*)(smem + A_QH);
    __nv_bfloat16* ql = (__nv_bfloat16*)(smem + A_QL);
    __nv_bfloat16* kh = (__nv_bfloat16*)(smem + A_KH);
    __nv_bfloat16* kl = (__nv_bfloat16*)(smem + A_KL);
    __nv_bfloat16* vh = (__nv_bfloat16*)(smem + A_VH);
    __nv_bfloat16* vl = (__nv_bfloat16*)(smem + A_VL);
    __nv_bfloat16* ph = (__nv_bfloat16*)(smem + A_PH);
    __nv_bfloat16* pl = (__nv_bfloat16*)(smem + A_PL);
    float*         sf = (float*)(smem + A_SF);
    float*         ls = (float*)(smem + A_LS);

    int t = threadIdx.x;
    int w = t >> 5;
    int row = t & 127;       // softmax row
    int half = t >> 7;       // 0: cols 0..31, 1: cols 32..63
    int qt = blockIdx.x;     // 0..15
    int nh = blockIdx.y;     // 0..31

    // load Q hi/lo (128 x 64 bf16 each)
    {
        const __nv_bfloat16* gqh = g_qh + ((size_t)nh * SLEN + (size_t)qt * 128) * HDIM;
        const __nv_bfloat16* gql = g_ql + ((size_t)nh * SLEN + (size_t)qt * 128) * HDIM;
        for (int i = t; i < 1024; i += 256) {
            int r = i >> 3, c = i & 7;
            *(uint4*)(qh + r * LDH + c * 8) = *(const uint4*)(gqh + (size_t)r * 64 + c * 8);
            *(uint4*)(ql + r * LDH + c * 8) = *(const uint4*)(gql + (size_t)r * 64 + c * 8);
        }
    }

    float lsum = 0.f;
    FragC oacc[4];
    #pragma unroll
    for (int n = 0; n < 4; n++) wmma::fill_fragment(oacc[n], 0.f);

    const float* mrow = mask + (size_t)(qt * 128 + row) * SLEN + half * 32;

    for (int kt = 0; kt < SLEN / 64; kt++) {
        // --- load K/V hi/lo tiles (64 x 64 bf16 each) ---
        {
            size_t gb = ((size_t)nh * SLEN + (size_t)kt * 64) * HDIM;
            for (int i = t; i < 512; i += 256) {
                int r = i >> 3, c = i & 7;
                size_t g = gb + (size_t)r * 64 + c * 8;
                int s = r * LDH + c * 8;
                *(uint4*)(kh + s) = *(const uint4*)(g_kh + g);
                *(uint4*)(kl + s) = *(const uint4*)(g_kl + g);
                *(uint4*)(vh + s) = *(const uint4*)(g_vh + g);
                *(uint4*)(vl + s) = *(const uint4*)(g_vl + g);
            }
        }
        __syncthreads();

        // --- S = Qh.Kh^T + Qh.Kl^T + Ql.Kh^T  (128x64) -> sf (aliased on P) ---
        {
            FragA aH[4], aL[4];
            #pragma unroll
            for (int kf = 0; kf < 4; kf++) {
                wmma::load_matrix_sync(aH[kf], qh + (w * 16) * LDH + kf * 16, LDH);
                wmma::load_matrix_sync(aL[kf], ql + (w * 16) * LDH + kf * 16, LDH);
            }
            FragC sacc[4];
            #pragma unroll
            for (int n = 0; n < 4; n++) wmma::fill_fragment(sacc[n], 0.f);

            #pragma unroll
            for (int n = 0; n < 4; n++) {
                #pragma unroll
                for (int kf = 0; kf < 4; kf++) {
                    FragBC bH, bL;
                    wmma::load_matrix_sync(bH, kh + (n * 16) * LDH + kf * 16, LDH);
                    wmma::mma_sync(sacc[n], aH[kf], bH, sacc[n]);
                    wmma::mma_sync(sacc[n], aL[kf], bH, sacc[n]);
                    wmma::load_matrix_sync(bL, kl + (n * 16) * LDH + kf * 16, LDH);
                    wmma::mma_sync(sacc[n], aH[kf], bL, sacc[n]);
                }
            }
            #pragma unroll
            for (int n = 0; n < 4; n++)
                wmma::store_matrix_sync(sf + (w * 16) * LDS + n * 16, sacc[n], LDS, wmma::mem_row_major);
        }
        __syncthreads();

        // --- softmax READ phase: all 256 threads, half row each ---
        float f[32];
        {
            const float4* srow = (const float4*)(sf + row * LDS + half * 32);
            const float4* mk4 = (const float4*)(mrow + kt * 64);
            #pragma unroll
            for (int c4 = 0; c4 < 8; c4++) {
                float4 s = srow[c4];
                float4 m = mk4[c4];
                float e0 = __expf(s.x * m.x);
                float e1 = __expf(s.y * m.y);
                float e2 = __expf(s.z * m.z);
                float e3 = __expf(s.w * m.w);
                lsum += e0 + e1 + e2 + e3;
                f[c4 * 4 + 0] = e0; f[c4 * 4 + 1] = e1;
                f[c4 * 4 + 2] = e2; f[c4 * 4 + 3] = e3;
            }
        }
        __syncthreads();   // all sf reads done before P overwrites (aliased)

        // --- softmax WRITE phase: pack bf16 hi/lo into ph/pl ---
        {
            uint4* phv = (uint4*)(ph + row * LDH + half * 32);
            uint4* plv = (uint4*)(pl + row * LDH + half * 32);
            #pragma unroll
            for (int j = 0; j < 4; j++) {
                float e0 = f[8 * j + 0], e1 = f[8 * j + 1], e2 = f[8 * j + 2], e3 = f[8 * j + 3];
                float e4 = f[8 * j + 4], e5 = f[8 * j + 5], e6 = f[8 * j + 6], e7 = f[8 * j + 7];
                phv[j] = make_uint4(pack_bf2(e0, e1), pack_bf2(e2, e3),
                                    pack_bf2(e4, e5), pack_bf2(e6, e7));
                plv[j] = make_uint4(
                    pack_bf2(e0 - bf_round(e0), e1 - bf_round(e1)),
                    pack_bf2(e2 - bf_round(e2), e3 - bf_round(e3)),
                    pack_bf2(e4 - bf_round(e4), e5 - bf_round(e5)),
                    pack_bf2(e6 - bf_round(e6), e7 - bf_round(e7)));
            }
        }
        __syncthreads();

        // --- O += Ph.Vh + Ph.Vl + Pl.Vh  (128x64, V row-major as B) ---
        {
            FragA pH[4], pL[4];
            #pragma unroll
            for (int kf = 0; kf < 4; kf++) {
                wmma::load_matrix_sync(pH[kf], ph + (w * 16) * LDH + kf * 16, LDH);
                wmma::load_matrix_sync(pL[kf], pl + (w * 16) * LDH + kf * 16, LDH);
            }
            #pragma unroll
            for (int n = 0; n < 4; n++) {
                #pragma unroll
                for (int kf = 0; kf < 4; kf++) {
                    FragBR bH, bL;
                    wmma::load_matrix_sync(bH, vh + (kf * 16) * LDH + n * 16, LDH);
                    wmma::mma_sync(oacc[n], pH[kf], bH, oacc[n]);
                    wmma::mma_sync(oacc[n], pL[kf], bH, oacc[n]);
                    wmma::load_matrix_sync(bL, vl + (kf * 16) * LDH + n * 16, LDH);
                    wmma::mma_sync(oacc[n], pH[kf], bL, oacc[n]);
                }
            }
        }
        __syncthreads();   // before next tile overwrites K/V/P/sf smem
    }

    // --- epilogue: combine lsum halves, normalize, split, store ---
    ls[t] = lsum;          // index = half*128 + row
    #pragma unroll
    for (int n = 0; n < 4; n++)
        wmma::store_matrix_sync(sf + (w * 16) * LDS + n * 16, oacc[n], LDS, wmma::mem_row_major);
    __syncthreads();

    {
        float inv = 1.f / (ls[row] + ls[128 + row]);
        int n = nh >> 4, h = nh & 15;
        size_t gbase = ((size_t)n * SLEN + (size_t)qt * 128 + row) * EMB + h * 64 + half * 32;
        const float* srow = sf + row * LDS + half * 32;
        #pragma unroll
        for (int j = 0; j < 4; j++) {
            float4 s0 = ((const float4*)srow)[2 * j];
            float4 s1 = ((const float4*)srow)[2 * j + 1];
            float o0 = s0.x * inv, o1 = s0.y * inv, o2 = s0.z * inv, o3 = s0.w * inv;
            float o4 = s1.x * inv, o5 = s1.y * inv, o6 = s1.z * inv, o7 = s1.w * inv;
            *(uint4*)(g_oh + gbase + j * 8) = make_uint4(
                pack_bf2(o0, o1), pack_bf2(o2, o3), pack_bf2(o4, o5), pack_bf2(o6, o7));
            *(uint4*)(g_ol + gbase + j * 8) = make_uint4(
                pack_bf2(o0 - bf_round(o0), o1 - bf_round(o1)),
                pack_bf2(o2 - bf_round(o2), o3 - bf_round(o3)),
                pack_bf2(o4 - bf_round(o4), o5 - bf_round(o5)),
                pack_bf2(o6 - bf_round(o6), o7 - bf_round(o7)));
        }
    }
}

// ---------------------------------------------------------------------------
// Kernel 4: output projection out[m][e] = att[m][:] . WoT[e][:] + bo[e]
// CTA = (et, mt): 128 m-rows x 64 e-cols, K=1024 in 16 chunks of 64.
// ---------------------------------------------------------------------------
#define P_AH 0
#define P_AL (P_AH + 128 * LDH * 2)
#define P_BH (P_AL + 128 * LDH * 2)
#define P_BL (P_BH + 64 * LDH * 2)
#define P_SF (P_BL + 64 * LDH * 2)
#define PROJ_SMEM (P_SF + 128 * LDS * 4)     // 90112

__global__ __launch_bounds__(256, 2) void outproj_wmma(
    const float* __restrict__ bo, float* __restrict__ out)
{
    extern __shared__ char smem[];
    __nv_bfloat16* ah = (__nv_bfloat16*)(smem + P_AH);
    __nv_bfloat16* al = (__nv_bfloat16*)(smem + P_AL);
    __nv_bfloat16* bh = (__nv_bfloat16*)(smem + P_BH);
    __nv_bfloat16* bl = (__nv_bfloat16*)(smem + P_BL);
    float*         sf = (float*)(smem + P_SF);

    int t = threadIdx.x;
    int w = t >> 5;
    int et = blockIdx.x;    // 0..15
    int mt = blockIdx.y;    // 0..31

    FragC oacc[4];
    #pragma unroll
    for (int n = 0; n < 4; n++) wmma::fill_fragment(oacc[n], 0.f);

    for (int kt = 0; kt < EMB / 64; kt++) {
        {
            const __nv_bfloat16* gah = g_oh + (size_t)(mt * 128) * EMB + kt * 64;
            const __nv_bfloat16* gal = g_ol + (size_t)(mt * 128) * EMB + kt * 64;
            for (int i = t; i < 1024; i += 256) {
                int r = i >> 3, c = i & 7;
                *(uint4*)(ah + r * LDH + c * 8) = *(const uint4*)(gah + (size_t)r * EMB + c * 8);
                *(uint4*)(al + r * LDH + c * 8) = *(const uint4*)(gal + (size_t)r * EMB + c * 8);
            }
            const __nv_bfloat16* gbh = g_woth + (size_t)(et * 64) * EMB + kt * 64;
            const __nv_bfloat16* gbl = g_wotl + (size_t)(et * 64) * EMB + kt * 64;
            for (int i = t; i < 512; i += 256) {
                int r = i >> 3, c = i & 7;
                *(uint4*)(bh + r * LDH + c * 8) = *(const uint4*)(gbh + (size_t)r * EMB + c * 8);
                *(uint4*)(bl + r * LDH + c * 8) = *(const uint4*)(gbl + (size_t)r * EMB + c * 8);
            }
        }
        __syncthreads();

        FragA aH[4], aL[4];
        #pragma unroll
        for (int kf = 0; kf < 4; kf++) {
            wmma::load_matrix_sync(aH[kf], ah + (w * 16) * LDH + kf * 16, LDH);
            wmma::load_matrix_sync(aL[kf], al + (w * 16) * LDH + kf * 16, LDH);
        }
        #pragma unroll
        for (int n = 0; n < 4; n++) {
            #pragma unroll
            for (int kf = 0; kf < 4; kf++) {
                FragBC bH, bL;
                wmma::load_matrix_sync(bH, bh + (n * 16) * LDH + kf * 16, LDH);
                wmma::mma_sync(oacc[n], aH[kf], bH, oacc[n]);
                wmma::mma_sync(oacc[n], aL[kf], bH, oacc[n]);
                wmma::load_matrix_sync(bL, bl + (n * 16) * LDH + kf * 16, LDH);
                wmma::mma_sync(oacc[n], aH[kf], bL, oacc[n]);
            }
        }
        __syncthreads();
    }

    #pragma unroll
    for (int n = 0; n < 4; n++)
        wmma::store_matrix_sync(sf + (w * 16) * LDS + n * 16, oacc[n], LDS, wmma::mem_row_major);
    __syncthreads();

    if (t < 128) {
        size_t m = (size_t)mt * 128 + t;
        float* dst = out + m * EMB + et * 64;
        const float* srow = sf + t * LDS;
        #pragma unroll
        for (int c4 = 0; c4 < 16; c4++) {
            float4 s = ((const float4*)srow)[c4];
            float4 bb = *(const float4*)&bo[et * 64 + c4 * 4];
            *(float4*)(dst + c4 * 4) = make_float4(s.x + bb.x, s.y + bb.y, s.z + bb.z, s.w + bb.w);
        }
    }
}

// ---------------------------------------------------------------------------
extern "C" void kernel_launch(void* const* d_in, const int* in_sizes, int n_in,
                              void* d_out, int out_size)
{
    const float* values  = (const float*)d_in[0];
    const float* keys    = (const float*)d_in[1];
    const float* queries = (const float*)d_in[2];
    const float* mask    = (const float*)d_in[3];
    const float* Wv = (const float*)d_in[4];
    const float* bv = (const float*)d_in[5];
    const float* Wk = (const float*)d_in[6];
    const float* bk = (const float*)d_in[7];
    const float* Wq = (const float*)d_in[8];
    const float* bq = (const float*)d_in[9];
    const float* Wo = (const float*)d_in[10];
    const float* bo = (const float*)d_in[11];
    float* out = (float*)d_out;

    cudaFuncSetAttribute(attn_wmma, cudaFuncAttributeMaxDynamicSharedMemorySize, ATTN_SMEM);
    cudaFuncSetAttribute(outproj_wmma, cudaFuncAttributeMaxDynamicSharedMemorySize, PROJ_SMEM);

    proj_kernel<<<NROWS / 64, 256>>>(values,  Wv, bv, 0, 1.0f);
    proj_kernel<<<NROWS / 64, 256>>>(keys,    Wk, bk, 1, 1.0f);
    proj_kernel<<<NROWS / 64, 256>>>(queries, Wq, bq, 2, 0.03125f);   // fold 1/sqrt(EMB)
    wo_convert<<<dim3(16, 16), 256>>>(Wo);

    attn_wmma<<<dim3(SLEN / 128, NH), 256, ATTN_SMEM>>>(mask);

    outproj_wmma<<<dim3(EMB / 64, NB * SLEN / 128), 256, PROJ_SMEM>>>(bo, out);
}

// round 12
// speedup vs baseline: 1.3562x; 1.3562x over previous
#include <cuda_runtime.h>
#include <cuda_bf16.h>
#include <mma.h>
#include <cstdint>
#include <math.h>

using namespace nvcuda;

#define NB 2
#define SLEN 2048
#define NHEADS 16
#define HDIM 64
#define EMB 1024
#define NH (NB * NHEADS)
#define NROWS (NB * SLEN * NHEADS)

// ---------------------------------------------------------------------------
// Global scratch (allocation-free rule: __device__ globals)
// ---------------------------------------------------------------------------
__device__ __align__(16) __nv_bfloat16 g_qh[(size_t)NH * SLEN * HDIM];
__device__ __align__(16) __nv_bfloat16 g_ql[(size_t)NH * SLEN * HDIM];
__device__ __align__(16) __nv_bfloat16 g_kh[(size_t)NH * SLEN * HDIM];
__device__ __align__(16) __nv_bfloat16 g_kl[(size_t)NH * SLEN * HDIM];
__device__ __align__(16) __nv_bfloat16 g_vh[(size_t)NH * SLEN * HDIM];
__device__ __align__(16) __nv_bfloat16 g_vl[(size_t)NH * SLEN * HDIM];
__device__ __align__(16) __nv_bfloat16 g_oh[(size_t)NB * SLEN * EMB];   // attn out hi
__device__ __align__(16) __nv_bfloat16 g_ol[(size_t)NB * SLEN * EMB];   // attn out lo
__device__ __align__(16) __nv_bfloat16 g_woth[(size_t)EMB * EMB];       // Wo^T hi (e,k)
__device__ __align__(16) __nv_bfloat16 g_wotl[(size_t)EMB * EMB];       // Wo^T lo (e,k)

__device__ __forceinline__ uint32_t pack_bf2(float a, float b) {
    __nv_bfloat16 x = __float2bfloat16(a), y = __float2bfloat16(b);
    return ((uint32_t)__bfloat16_as_ushort(y) << 16) | (uint32_t)__bfloat16_as_ushort(x);
}
__device__ __forceinline__ float bf_round(float a) {
    return __bfloat162float(__float2bfloat16(a));
}

// ---------------------------------------------------------------------------
// Kernel 1: per-head projection -> bf16 hi/lo splits in (N,H,S,D)
// ---------------------------------------------------------------------------
__global__ __launch_bounds__(256) void proj_kernel(
    const float* __restrict__ in, const float* __restrict__ W,
    const float* __restrict__ bias, int which, float scale)
{
    __shared__ float in_s[64 * 65];
    __shared__ float w_s[64 * 64];

    __nv_bfloat16* outh = (which == 0) ? g_vh : (which == 1) ? g_kh : g_qh;
    __nv_bfloat16* outl = (which == 0) ? g_vl : (which == 1) ? g_kl : g_ql;

    int t = threadIdx.x;
    int rowBase = blockIdx.x * 64;

    for (int i = t; i < 4096; i += 256) w_s[i] = W[i];
    for (int i = t; i < 4096; i += 256) {
        int r = i >> 6, k = i & 63;
        in_s[r * 65 + k] = in[(size_t)rowBase * 64 + i];
    }
    __syncthreads();

    int tr = t >> 4, tc = t & 15;
    int r0 = tr * 4, c0 = tc * 4;

    float acc[4][4];
    #pragma unroll
    for (int u = 0; u < 4; u++)
        #pragma unroll
        for (int v = 0; v < 4; v++) acc[u][v] = bias[c0 + v];

    #pragma unroll 8
    for (int k = 0; k < 64; k++) {
        float4 b = *(const float4*)&w_s[k * 64 + c0];
        float a[4];
        #pragma unroll
        for (int u = 0; u < 4; u++) a[u] = in_s[(r0 + u) * 65 + k];
        #pragma unroll
        for (int u = 0; u < 4; u++) {
            acc[u][0] += a[u] * b.x; acc[u][1] += a[u] * b.y;
            acc[u][2] += a[u] * b.z; acc[u][3] += a[u] * b.w;
        }
    }

    #pragma unroll
    for (int u = 0; u < 4; u++) {
        int row = rowBase + r0 + u;
        int n = row >> 15;
        int rem = row & 32767;
        int s = rem >> 4;
        int h = rem & 15;
        size_t base = (((size_t)(n * NHEADS + h)) * SLEN + s) * HDIM + c0;
        float v0 = acc[u][0] * scale, v1 = acc[u][1] * scale;
        float v2 = acc[u][2] * scale, v3 = acc[u][3] * scale;
        *(uint32_t*)&outh[base + 0] = pack_bf2(v0, v1);
        *(uint32_t*)&outh[base + 2] = pack_bf2(v2, v3);
        *(uint32_t*)&outl[base + 0] = pack_bf2(v0 - bf_round(v0), v1 - bf_round(v1));
        *(uint32_t*)&outl[base + 2] = pack_bf2(v2 - bf_round(v2), v3 - bf_round(v3));
    }
}

// ---------------------------------------------------------------------------
// Kernel 2: transpose + split Wo -> WoT hi/lo (e,k)
// ---------------------------------------------------------------------------
__global__ __launch_bounds__(256) void wo_convert(const float* __restrict__ Wo)
{
    __shared__ float ts[64 * 65];
    int t = threadIdx.x;
    int kb = blockIdx.x * 64, eb = blockIdx.y * 64;
    for (int i = t; i < 4096; i += 256) {
        int r = i >> 6, c = i & 63;
        ts[c * 65 + r] = Wo[(size_t)(kb + r) * EMB + eb + c];
    }
    __syncthreads();
    for (int i = t; i < 4096; i += 256) {
        int e = i >> 6, k = i & 63;
        float v = ts[e * 65 + k];
        size_t o = (size_t)(eb + e) * EMB + kb + k;
        g_woth[o] = __float2bfloat16(v);
        g_wotl[o] = __float2bfloat16(v - bf_round(v));
    }
}

// ---------------------------------------------------------------------------
// Kernel 3: WMMA flash attention. CTA = (qt, nh): 128 q-rows x full S.
// KV tile = 128 (16 iterations). Q fragments hoisted out of the KV loop.
// sf (f32 scores, 128x128) aliased over ph/pl. 176KB smem, 1 CTA/SM.
// ---------------------------------------------------------------------------
#define LDH 72                 // bf16 ldm for 64-col arrays (Q,K,V)
#define LDP 136                // bf16 ldm for 128-col P
#define LDSF 132               // f32 ldm for 128-col scores

#define TS 128                 // KV tile size

#define A_QH 0
#define A_QL (A_QH + 128 * LDH * 2)          // 18432
#define A_KH (A_QL + 128 * LDH * 2)          // 36864
#define A_KL (A_KH + TS * LDH * 2)           // 55296
#define A_VH (A_KL + TS * LDH * 2)           // 73728
#define A_VL (A_VH + TS * LDH * 2)           // 92160
#define A_PH (A_VL + TS * LDH * 2)           // 110592
#define A_PL (A_PH + 128 * LDP * 2)          // 145408
#define A_SF A_PH                            // aliased: 128*132*4=67584 <= 69632
#define A_LS (A_PL + 128 * LDP * 2)          // 180224
#define ATTN_SMEM (A_LS + 256 * 4)           // 181248 (177KB) -> 1 CTA/SM

typedef wmma::fragment<wmma::matrix_a, 16, 16, 16, __nv_bfloat16, wmma::row_major> FragA;
typedef wmma::fragment<wmma::matrix_b, 16, 16, 16, __nv_bfloat16, wmma::col_major> FragBC;
typedef wmma::fragment<wmma::matrix_b, 16, 16, 16, __nv_bfloat16, wmma::row_major> FragBR;
typedef wmma::fragment<wmma::accumulator, 16, 16, 16, float> FragC;

__global__ __launch_bounds__(256) void attn_wmma(const float* __restrict__ mask)
{
    extern __shared__ char smem[];
    __nv_bfloat16* qh = (__nv_bfloat16*)(smem + A_QH);
    __nv_bfloat16* ql = (__nv_bfloat16*)(smem + A_QL);
    __nv_bfloat16* kh = (__nv_bfloat16*)(smem + A_KH);
    __nv_bfloat16* kl = (__nv_bfloat16*)(smem + A_KL);
    __nv_bfloat16* vh = (__nv_bfloat16*)(smem + A_VH);
    __nv_bfloat16* vl = (__nv_bfloat16*)(smem + A_VL);
    __nv_bfloat16* ph = (__nv_bfloat16*)(smem + A_PH);
    __nv_bfloat16* pl = (__nv_bfloat16*)(smem + A_PL);
    float*         sf = (float*)(smem + A_SF);
    float*         ls = (float*)(smem + A_LS);

    int t = threadIdx.x;
    int w = t >> 5;
    int row = t & 127;       // softmax row
    int half = t >> 7;       // 0: cols 0..63, 1: cols 64..127 (of the 128-tile)
    int qt = blockIdx.x;     // 0..15
    int nh = blockIdx.y;     // 0..31

    // load Q hi/lo (128 x 64 bf16 each)
    {
        const __nv_bfloat16* gqh = g_qh + ((size_t)nh * SLEN + (size_t)qt * 128) * HDIM;
        const __nv_bfloat16* gql = g_ql + ((size_t)nh * SLEN + (size_t)qt * 128) * HDIM;
        for (int i = t; i < 1024; i += 256) {
            int r = i >> 3, c = i & 7;
            *(uint4*)(qh + r * LDH + c * 8) = *(const uint4*)(gqh + (size_t)r * 64 + c * 8);
            *(uint4*)(ql + r * LDH + c * 8) = *(const uint4*)(gql + (size_t)r * 64 + c * 8);
        }
    }
    __syncthreads();

    // hoist Q fragments: loop-invariant across all KV tiles
    FragA aH[4], aL[4];
    #pragma unroll
    for (int kf = 0; kf < 4; kf++) {
        wmma::load_matrix_sync(aH[kf], qh + (w * 16) * LDH + kf * 16, LDH);
        wmma::load_matrix_sync(aL[kf], ql + (w * 16) * LDH + kf * 16, LDH);
    }

    float lsum = 0.f;
    FragC oacc[4];
    #pragma unroll
    for (int n = 0; n < 4; n++) wmma::fill_fragment(oacc[n], 0.f);

    const float* mrow = mask + (size_t)(qt * 128 + row) * SLEN + half * 64;

    for (int kt = 0; kt < SLEN / TS; kt++) {
        // --- load K/V hi/lo tiles (128 x 64 bf16 each) ---
        {
            size_t gb = ((size_t)nh * SLEN + (size_t)kt * TS) * HDIM;
            for (int i = t; i < 1024; i += 256) {
                int r = i >> 3, c = i & 7;
                size_t g = gb + (size_t)r * 64 + c * 8;
                int s = r * LDH + c * 8;
                *(uint4*)(kh + s) = *(const uint4*)(g_kh + g);
                *(uint4*)(kl + s) = *(const uint4*)(g_kl + g);
                *(uint4*)(vh + s) = *(const uint4*)(g_vh + g);
                *(uint4*)(vl + s) = *(const uint4*)(g_vl + g);
            }
        }
        __syncthreads();

        // --- S = Qh.Kh^T + Qh.Kl^T + Ql.Kh^T  (128x128) -> sf (aliased on P) ---
        {
            FragC sacc[8];
            #pragma unroll
            for (int n = 0; n < 8; n++) wmma::fill_fragment(sacc[n], 0.f);

            #pragma unroll
            for (int n = 0; n < 8; n++) {
                #pragma unroll
                for (int kf = 0; kf < 4; kf++) {
                    FragBC bH, bL;
                    wmma::load_matrix_sync(bH, kh + (n * 16) * LDH + kf * 16, LDH);
                    wmma::mma_sync(sacc[n], aH[kf], bH, sacc[n]);
                    wmma::mma_sync(sacc[n], aL[kf], bH, sacc[n]);
                    wmma::load_matrix_sync(bL, kl + (n * 16) * LDH + kf * 16, LDH);
                    wmma::mma_sync(sacc[n], aH[kf], bL, sacc[n]);
                }
            }
            #pragma unroll
            for (int n = 0; n < 8; n++)
                wmma::store_matrix_sync(sf + (w * 16) * LDSF + n * 16, sacc[n], LDSF, wmma::mem_row_major);
        }
        __syncthreads();

        // --- softmax READ phase: all 256 threads, half row (64 cols) each ---
        float f[64];
        {
            const float4* srow = (const float4*)(sf + row * LDSF + half * 64);
            const float4* mk4 = (const float4*)(mrow + kt * TS);
            #pragma unroll
            for (int c4 = 0; c4 < 16; c4++) {
                float4 s = srow[c4];
                float4 m = mk4[c4];
                float e0 = __expf(s.x * m.x);
                float e1 = __expf(s.y * m.y);
                float e2 = __expf(s.z * m.z);
                float e3 = __expf(s.w * m.w);
                lsum += e0 + e1 + e2 + e3;
                f[c4 * 4 + 0] = e0; f[c4 * 4 + 1] = e1;
                f[c4 * 4 + 2] = e2; f[c4 * 4 + 3] = e3;
            }
        }
        __syncthreads();   // all sf reads done before P overwrites (aliased)

        // --- softmax WRITE phase: pack bf16 hi/lo into ph/pl ---
        {
            uint4* phv = (uint4*)(ph + row * LDP + half * 64);
            uint4* plv = (uint4*)(pl + row * LDP + half * 64);
            #pragma unroll
            for (int j = 0; j < 8; j++) {
                float e0 = f[8 * j + 0], e1 = f[8 * j + 1], e2 = f[8 * j + 2], e3 = f[8 * j + 3];
                float e4 = f[8 * j + 4], e5 = f[8 * j + 5], e6 = f[8 * j + 6], e7 = f[8 * j + 7];
                phv[j] = make_uint4(pack_bf2(e0, e1), pack_bf2(e2, e3),
                                    pack_bf2(e4, e5), pack_bf2(e6, e7));
                plv[j] = make_uint4(
                    pack_bf2(e0 - bf_round(e0), e1 - bf_round(e1)),
                    pack_bf2(e2 - bf_round(e2), e3 - bf_round(e3)),
                    pack_bf2(e4 - bf_round(e4), e5 - bf_round(e5)),
                    pack_bf2(e6 - bf_round(e6), e7 - bf_round(e7)));
            }
        }
        __syncthreads();

        // --- O += Ph.Vh + Ph.Vl + Pl.Vh  (128x64, K-dim = 128) ---
        {
            #pragma unroll
            for (int kf = 0; kf < 8; kf++) {
                FragA pH, pL;
                wmma::load_matrix_sync(pH, ph + (w * 16) * LDP + kf * 16, LDP);
                wmma::load_matrix_sync(pL, pl + (w * 16) * LDP + kf * 16, LDP);
                #pragma unroll
                for (int n = 0; n < 4; n++) {
                    FragBR bH, bL;
                    wmma::load_matrix_sync(bH, vh + (kf * 16) * LDH + n * 16, LDH);
                    wmma::mma_sync(oacc[n], pH, bH, oacc[n]);
                    wmma::mma_sync(oacc[n], pL, bH, oacc[n]);
                    wmma::load_matrix_sync(bL, vl + (kf * 16) * LDH + n * 16, LDH);
                    wmma::mma_sync(oacc[n], pH, bL, oacc[n]);
                }
            }
        }
        __syncthreads();   // before next tile overwrites K/V/P/sf smem
    }

    // --- epilogue: combine lsum halves, normalize, split, store ---
    ls[t] = lsum;          // index = half*128 + row
    #pragma unroll
    for (int n = 0; n < 4; n++)
        wmma::store_matrix_sync(sf + (w * 16) * LDSF + n * 16, oacc[n], LDSF, wmma::mem_row_major);
    __syncthreads();

    {
        float inv = 1.f / (ls[row] + ls[128 + row]);
        int n = nh >> 4, h = nh & 15;
        size_t gbase = ((size_t)n * SLEN + (size_t)qt * 128 + row) * EMB + h * 64 + half * 32;
        const float* srow = sf + row * LDSF + half * 32;
        #pragma unroll
        for (int j = 0; j < 4; j++) {
            float4 s0 = ((const float4*)srow)[2 * j];
            float4 s1 = ((const float4*)srow)[2 * j + 1];
            float o0 = s0.x * inv, o1 = s0.y * inv, o2 = s0.z * inv, o3 = s0.w * inv;
            float o4 = s1.x * inv, o5 = s1.y * inv, o6 = s1.z * inv, o7 = s1.w * inv;
            *(uint4*)(g_oh + gbase + j * 8) = make_uint4(
                pack_bf2(o0, o1), pack_bf2(o2, o3), pack_bf2(o4, o5), pack_bf2(o6, o7));
            *(uint4*)(g_ol + gbase + j * 8) = make_uint4(
                pack_bf2(o0 - bf_round(o0), o1 - bf_round(o1)),
                pack_bf2(o2 - bf_round(o2), o3 - bf_round(o3)),
                pack_bf2(o4 - bf_round(o4), o5 - bf_round(o5)),
                pack_bf2(o6 - bf_round(o6), o7 - bf_round(o7)));
        }
    }
}

// ---------------------------------------------------------------------------
// Kernel 4: output projection out[m][e] = att[m][:] . WoT[e][:] + bo[e]
// CTA = (et, mt): 128 m-rows x 64 e-cols, K=1024 in 16 chunks of 64.
// ---------------------------------------------------------------------------
#define LDS 68
#define P_AH 0
#define P_AL (P_AH + 128 * LDH * 2)
#define P_BH (P_AL + 128 * LDH * 2)
#define P_BL (P_BH + 64 * LDH * 2)
#define P_SF (P_BL + 64 * LDH * 2)
#define PROJ_SMEM (P_SF + 128 * LDS * 4)     // 90112

__global__ __launch_bounds__(256) void outproj_wmma(
    const float* __restrict__ bo, float* __restrict__ out)
{
    extern __shared__ char smem[];
    __nv_bfloat16* ah = (__nv_bfloat16*)(smem + P_AH);
    __nv_bfloat16* al = (__nv_bfloat16*)(smem + P_AL);
    __nv_bfloat16* bh = (__nv_bfloat16*)(smem + P_BH);
    __nv_bfloat16* bl = (__nv_bfloat16*)(smem + P_BL);
    float*         sf = (float*)(smem + P_SF);

    int t = threadIdx.x;
    int w = t >> 5;
    int et = blockIdx.x;    // 0..15
    int mt = blockIdx.y;    // 0..31

    FragC oacc[4];
    #pragma unroll
    for (int n = 0; n < 4; n++) wmma::fill_fragment(oacc[n], 0.f);

    for (int kt = 0; kt < EMB / 64; kt++) {
        {
            const __nv_bfloat16* gah = g_oh + (size_t)(mt * 128) * EMB + kt * 64;
            const __nv_bfloat16* gal = g_ol + (size_t)(mt * 128) * EMB + kt * 64;
            for (int i = t; i < 1024; i += 256) {
                int r = i >> 3, c = i & 7;
                *(uint4*)(ah + r * LDH + c * 8) = *(const uint4*)(gah + (size_t)r * EMB + c * 8);
                *(uint4*)(al + r * LDH + c * 8) = *(const uint4*)(gal + (size_t)r * EMB + c * 8);
            }
            const __nv_bfloat16* gbh = g_woth + (size_t)(et * 64) * EMB + kt * 64;
            const __nv_bfloat16* gbl = g_wotl + (size_t)(et * 64) * EMB + kt * 64;
            for (int i = t; i < 512; i += 256) {
                int r = i >> 3, c = i & 7;
                *(uint4*)(bh + r * LDH + c * 8) = *(const uint4*)(gbh + (size_t)r * EMB + c * 8);
                *(uint4*)(bl + r * LDH + c * 8) = *(const uint4*)(gbl + (size_t)r * EMB + c * 8);
            }
        }
        __syncthreads();

        FragA aH[4], aL[4];
        #pragma unroll
        for (int kf = 0; kf < 4; kf++) {
            wmma::load_matrix_sync(aH[kf], ah + (w * 16) * LDH + kf * 16, LDH);
            wmma::load_matrix_sync(aL[kf], al + (w * 16) * LDH + kf * 16, LDH);
        }
        #pragma unroll
        for (int n = 0; n < 4; n++) {
            #pragma unroll
            for (int kf = 0; kf < 4; kf++) {
                FragBC bH, bL;
                wmma::load_matrix_sync(bH, bh + (n * 16) * LDH + kf * 16, LDH);
                wmma::mma_sync(oacc[n], aH[kf], bH, oacc[n]);
                wmma::mma_sync(oacc[n], aL[kf], bH, oacc[n]);
                wmma::load_matrix_sync(bL, bl + (n * 16) * LDH + kf * 16, LDH);
                wmma::mma_sync(oacc[n], aH[kf], bL, oacc[n]);
            }
        }
        __syncthreads();
    }

    #pragma unroll
    for (int n = 0; n < 4; n++)
        wmma::store_matrix_sync(sf + (w * 16) * LDS + n * 16, oacc[n], LDS, wmma::mem_row_major);
    __syncthreads();

    if (t < 128) {
        size_t m = (size_t)mt * 128 + t;
        float* dst = out + m * EMB + et * 64;
        const float* srow = sf + t * LDS;
        #pragma unroll
        for (int c4 = 0; c4 < 16; c4++) {
            float4 s = ((const float4*)srow)[c4];
            float4 bb = *(const float4*)&bo[et * 64 + c4 * 4];
            *(float4*)(dst + c4 * 4) = make_float4(s.x + bb.x, s.y + bb.y, s.z + bb.z, s.w + bb.w);
        }
    }
}

// ---------------------------------------------------------------------------
extern "C" void kernel_launch(void* const* d_in, const int* in_sizes, int n_in,
                              void* d_out, int out_size)
{
    const float* values  = (const float*)d_in[0];
    const float* keys    = (const float*)d_in[1];
    const float* queries = (const float*)d_in[2];
    const float* mask    = (const float*)d_in[3];
    const float* Wv = (const float*)d_in[4];
    const float* bv = (const float*)d_in[5];
    const float* Wk = (const float*)d_in[6];
    const float* bk = (const float*)d_in[7];
    const float* Wq = (const float*)d_in[8];
    const float* bq = (const float*)d_in[9];
    const float* Wo = (const float*)d_in[10];
    const float* bo = (const float*)d_in[11];
    float* out = (float*)d_out;

    cudaFuncSetAttribute(attn_wmma, cudaFuncAttributeMaxDynamicSharedMemorySize, ATTN_SMEM);
    cudaFuncSetAttribute(outproj_wmma, cudaFuncAttributeMaxDynamicSharedMemorySize, PROJ_SMEM);

    proj_kernel<<<NROWS / 64, 256>>>(values,  Wv, bv, 0, 1.0f);
    proj_kernel<<<NROWS / 64, 256>>>(keys,    Wk, bk, 1, 1.0f);
    proj_kernel<<<NROWS / 64, 256>>>(queries, Wq, bq, 2, 0.03125f);   // fold 1/sqrt(EMB)
    wo_convert<<<dim3(16, 16), 256>>>(Wo);

    attn_wmma<<<dim3(SLEN / 128, NH), 256, ATTN_SMEM>>>(mask);

    outproj_wmma<<<dim3(EMB / 64, NB * SLEN / 128), 256, PROJ_SMEM>>>(bo, out);
}